// round 15
// baseline (speedup 1.0000x reference)
#include <cuda_runtime.h>
#include <cuda_bf16.h>
#include <math.h>
#include <stdint.h>

// ---------------------------------------------------------------------------
// HermitianAttention (B=2,S=2048,D=1024,H=16,hd=64) — bf16x3, pre-packed.
// R15 = R12 (best measured: Karatsuba linears, [kpair][n] weights, ldmatrix
// A/Q, ldsm2 K) + GEMM occupancy 3 CTAs/SM + fused pack_w3 launch.
// ---------------------------------------------------------------------------

#define BATCH 2
#define SEQ   2048
#define DIMM  1024
#define NH    16
#define HD    64
#define NTOK  (BATCH * SEQ)
#define NTD   (NTOK * DIMM)
#define KP    1024
#define AS    1536
#define XR    0
#define XI    512
#define XA    1024

#define MEGA (1024u * 1024u)
__device__ uint32_t g_scratch[72u * MEGA];

__device__ __forceinline__ void cvt2(float x0, float x1, uint32_t& h, uint32_t& l) {
    __nv_bfloat16 h0 = __float2bfloat16_rn(x0);
    __nv_bfloat16 h1 = __float2bfloat16_rn(x1);
    float r0 = x0 - __bfloat162float(h0);
    float r1 = x1 - __bfloat162float(h1);
    __nv_bfloat16 l0 = __float2bfloat16_rn(r0);
    __nv_bfloat16 l1 = __float2bfloat16_rn(r1);
    h = ((uint32_t)__bfloat16_as_ushort(h1) << 16) | __bfloat16_as_ushort(h0);
    l = ((uint32_t)__bfloat16_as_ushort(l1) << 16) | __bfloat16_as_ushort(l0);
}

__device__ __forceinline__ void mma16(float c[4], const uint32_t a[4], const uint32_t b[2]) {
    asm volatile(
        "mma.sync.aligned.m16n8k16.row.col.f32.bf16.bf16.f32 "
        "{%0,%1,%2,%3}, {%4,%5,%6,%7}, {%8,%9}, {%0,%1,%2,%3};\n"
        : "+f"(c[0]), "+f"(c[1]), "+f"(c[2]), "+f"(c[3])
        : "r"(a[0]), "r"(a[1]), "r"(a[2]), "r"(a[3]), "r"(b[0]), "r"(b[1]));
}

__device__ __forceinline__ void cpa16(const void* dst, const void* src) {
    uint32_t d = (uint32_t)__cvta_generic_to_shared(dst);
    asm volatile("cp.async.cg.shared.global [%0], [%1], 16;\n" :: "r"(d), "l"(src));
}
#define CP_COMMIT() asm volatile("cp.async.commit_group;\n" ::: "memory")

__device__ __forceinline__ void ldsm4(uint32_t r[4], const void* p) {
    uint32_t a = (uint32_t)__cvta_generic_to_shared(p);
    asm volatile("ldmatrix.sync.aligned.m8n8.x4.shared.b16 {%0,%1,%2,%3}, [%4];"
        : "=r"(r[0]), "=r"(r[1]), "=r"(r[2]), "=r"(r[3]) : "r"(a));
}
__device__ __forceinline__ void ldsm2(uint32_t r[2], const void* p) {
    uint32_t a = (uint32_t)__cvta_generic_to_shared(p);
    asm volatile("ldmatrix.sync.aligned.m8n8.x2.shared.b16 {%0,%1}, [%2];"
        : "=r"(r[0]), "=r"(r[1]) : "r"(a));
}

// ---------------------------------------------------------------------------
// Pack kernels.
// ---------------------------------------------------------------------------
__global__ void pack_x(const float* __restrict__ zr, const float* __restrict__ zi,
                       uint32_t* __restrict__ Ah, uint32_t* __restrict__ Al)
{
    int p = blockIdx.x * blockDim.x + threadIdx.x;
    int m = p / AS, j = p % AS;
    int c = (j & 511) * 2;
    float a, b;
    if (j < 512)       { float2 v = *(const float2*)(zr + (size_t)m * DIMM + c); a = v.x; b = v.y; }
    else if (j < 1024) { float2 v = *(const float2*)(zi + (size_t)m * DIMM + c); a = v.x; b = v.y; }
    else {
        float2 vr = *(const float2*)(zr + (size_t)m * DIMM + c);
        float2 vi = *(const float2*)(zi + (size_t)m * DIMM + c);
        a = vr.x + vi.x; b = vr.y + vi.y;
    }
    uint32_t h, l; cvt2(a, b, h, l);
    Ah[p] = h; Al[p] = l;
}

#define BSEG (512u * 1024u)
// Fused over z: all 4 weight matrices in one launch.
__global__ void pack_w3_all(const float* __restrict__ Wq_r, const float* __restrict__ Wq_i,
                            const float* __restrict__ Wk_r, const float* __restrict__ Wk_i,
                            const float* __restrict__ Wv_r, const float* __restrict__ Wv_i,
                            const float* __restrict__ Wo_r, const float* __restrict__ Wo_i,
                            uint32_t* __restrict__ Bqh, uint32_t* __restrict__ Bql,
                            uint32_t* __restrict__ Bkh, uint32_t* __restrict__ Bkl,
                            uint32_t* __restrict__ Bvh, uint32_t* __restrict__ Bvl,
                            uint32_t* __restrict__ Boh, uint32_t* __restrict__ Bol)
{
    const float *Wr, *Wi; uint32_t *Bh, *Bl;
    if (blockIdx.y == 0)      { Wr = Wq_r; Wi = Wq_i; Bh = Bqh; Bl = Bql; }
    else if (blockIdx.y == 1) { Wr = Wk_r; Wi = Wk_i; Bh = Bkh; Bl = Bkl; }
    else if (blockIdx.y == 2) { Wr = Wv_r; Wi = Wv_i; Bh = Bvh; Bl = Bvl; }
    else                      { Wr = Wo_r; Wi = Wo_i; Bh = Boh; Bl = Bol; }

    int idx = blockIdx.x * blockDim.x + threadIdx.x;
    int n = idx & 1023, pp = idx >> 10;
    int k0 = 2 * pp;
    float wr0 = Wr[(size_t)k0 * DIMM + n], wr1 = Wr[(size_t)(k0 + 1) * DIMM + n];
    float wi0 = Wi[(size_t)k0 * DIMM + n], wi1 = Wi[(size_t)(k0 + 1) * DIMM + n];
    uint32_t h, l;
    size_t o = (size_t)pp * 1024 + n;
    cvt2(wr0, wr1, h, l);                    Bh[o] = h;            Bl[o] = l;
    cvt2(-(wr0 + wi0), -(wr1 + wi1), h, l);  Bh[o + BSEG] = h;     Bl[o + BSEG] = l;
    cvt2(wi0 - wr0, wi1 - wr1, h, l);        Bh[o + 2 * BSEG] = h; Bl[o + 2 * BSEG] = l;
}

// ---------------------------------------------------------------------------
// bf16x3 GEMM (R12 body; occupancy target 3 CTAs/SM).
// M=4096, Kpairs=512, N=1024. BM=BN=128, BK=16 pairs, 32 stages.
// 128 threads, 4 warps (2x2), warp tile 64x64.
// ---------------------------------------------------------------------------
struct GSmem {
    uint32_t Ah[2][128][20], Al[2][128][20];
    uint32_t Bh[2][16][136], Bl[2][16][136];
};

__device__ __forceinline__ void
gemm_body(GSmem& sm,
          const uint32_t* __restrict__ Ah, const uint32_t* __restrict__ Al,
          const uint32_t* __restrict__ Bh, const uint32_t* __restrict__ Bl,
          const float* __restrict__ k1,
          uint32_t* __restrict__ Yh, uint32_t* __restrict__ Yl, int co,
          float* __restrict__ Yf, int mode, float oscale)
{
    const int tid = threadIdx.x;
    const int w = tid >> 5, lane = tid & 31;
    const int grp = lane >> 2, tk = lane & 3;
    const int warpM = (w >> 1) * 64;
    const int warpN = (w & 1) * 64;
    const int bm = blockIdx.y * 128;
    const int bn = blockIdx.x * 128;
    const int lrow = lane & 15;
    const int lcol = (lane >> 4) * 4;

    float acc[4][8][4];
    #pragma unroll
    for (int mi = 0; mi < 4; mi++)
        #pragma unroll
        for (int ni = 0; ni < 8; ni++)
            #pragma unroll
            for (int v = 0; v < 4; v++) acc[mi][ni][v] = 0.0f;

    auto fill = [&](int s, int kp) {
        #pragma unroll
        for (int it = 0; it < 8; it++) {
            int t = tid + it * 128;
            int t2 = t & 511;
            int r = t2 >> 2, c = (t2 & 3) * 4;
            const uint32_t* src = (t < 512 ? Ah : Al) + (size_t)(bm + r) * AS + kp + c;
            if (t < 512) cpa16(&sm.Ah[s][r][c], src);
            else         cpa16(&sm.Al[s][r][c], src);
        }
        #pragma unroll
        for (int it = 0; it < 8; it++) {
            int t = tid + it * 128;
            int t2 = t & 511;
            int p = t2 >> 5, c = (t2 & 31) * 4;
            const uint32_t* src = (t < 512 ? Bh : Bl) + (size_t)(kp + p) * 1024 + bn + c;
            if (t < 512) cpa16(&sm.Bh[s][p][c], src);
            else         cpa16(&sm.Bl[s][p][c], src);
        }
    };

    fill(0, 0);
    CP_COMMIT();

    for (int st = 0; st < 32; st++) {
        int cur = st & 1;
        if (st + 1 < 32) {
            fill(cur ^ 1, (st + 1) * 16);
            CP_COMMIT();
            asm volatile("cp.async.wait_group 1;\n" ::: "memory");
        } else {
            asm volatile("cp.async.wait_group 0;\n" ::: "memory");
        }
        __syncthreads();

        #pragma unroll
        for (int kk = 0; kk < 2; kk++) {
            uint32_t afh[4][4], afl[4][4];
            #pragma unroll
            for (int mi = 0; mi < 4; mi++) {
                int m0 = warpM + mi * 16;
                ldsm4(afh[mi], &sm.Ah[cur][m0 + lrow][kk * 8 + lcol]);
                ldsm4(afl[mi], &sm.Al[cur][m0 + lrow][kk * 8 + lcol]);
            }
            #pragma unroll
            for (int ni = 0; ni < 8; ni++) {
                int n0 = warpN + ni * 8;
                uint32_t bfh[2], bfl[2];
                bfh[0] = sm.Bh[cur][kk * 8 + tk    ][n0 + grp];
                bfh[1] = sm.Bh[cur][kk * 8 + tk + 4][n0 + grp];
                bfl[0] = sm.Bl[cur][kk * 8 + tk    ][n0 + grp];
                bfl[1] = sm.Bl[cur][kk * 8 + tk + 4][n0 + grp];
                #pragma unroll
                for (int mi = 0; mi < 4; mi++) {
                    mma16(acc[mi][ni], afh[mi], bfh);
                    mma16(acc[mi][ni], afh[mi], bfl);
                    mma16(acc[mi][ni], afl[mi], bfh);
                }
            }
        }
        __syncthreads();
    }

    #pragma unroll
    for (int mi = 0; mi < 4; mi++) {
        int m = bm + warpM + mi * 16 + grp;
        #pragma unroll
        for (int ni = 0; ni < 8; ni++) {
            int n = bn + warpN + ni * 8 + tk * 2;
            if (mode == 0) {
                *(float2*)(Yf + (size_t)m * 1024 + n) =
                    make_float2(acc[mi][ni][0], acc[mi][ni][1]);
                *(float2*)(Yf + (size_t)(m + 8) * 1024 + n) =
                    make_float2(acc[mi][ni][2], acc[mi][ni][3]);
            } else {
                float2 k0 = *(const float2*)(k1 + (size_t)m * 1024 + n);
                float2 k8 = *(const float2*)(k1 + (size_t)(m + 8) * 1024 + n);
                float v0 = acc[mi][ni][0] + k0.x, v1 = acc[mi][ni][1] + k0.y;
                float v2 = acc[mi][ni][2] + k8.x, v3 = acc[mi][ni][3] + k8.y;
                if (mode == 1) {
                    uint32_t h, l;
                    int col = co + (n >> 1);
                    cvt2(v0 * oscale, v1 * oscale, h, l);
                    Yh[(size_t)m * KP + col] = h;
                    Yl[(size_t)m * KP + col] = l;
                    cvt2(v2 * oscale, v3 * oscale, h, l);
                    Yh[(size_t)(m + 8) * KP + col] = h;
                    Yl[(size_t)(m + 8) * KP + col] = l;
                } else {
                    *(float2*)(Yf + (size_t)m * 1024 + n) = make_float2(v0, v1);
                    *(float2*)(Yf + (size_t)(m + 8) * 1024 + n) = make_float2(v2, v3);
                }
            }
        }
    }
}

__global__ void __launch_bounds__(128, 3)
gemm_k1_qkv(const uint32_t* __restrict__ Ah, const uint32_t* __restrict__ Al,
            const uint32_t* __restrict__ Bqh, const uint32_t* __restrict__ Bql,
            const uint32_t* __restrict__ Bkh, const uint32_t* __restrict__ Bkl,
            const uint32_t* __restrict__ Bvh, const uint32_t* __restrict__ Bvl,
            float* __restrict__ k1q, float* __restrict__ k1k, float* __restrict__ k1v)
{
    __shared__ GSmem sm;
    const uint32_t *Bh, *Bl; float* Yf;
    if (blockIdx.z == 0)      { Bh = Bqh; Bl = Bql; Yf = k1q; }
    else if (blockIdx.z == 1) { Bh = Bkh; Bl = Bkl; Yf = k1k; }
    else                      { Bh = Bvh; Bl = Bvl; Yf = k1v; }
    gemm_body(sm, Ah, Al, Bh, Bl, nullptr, nullptr, nullptr, 0, Yf, 0, 1.0f);
}

__global__ void __launch_bounds__(128, 3)
gemm_comb_qkv(const uint32_t* __restrict__ Azh, const uint32_t* __restrict__ Azl,
              const uint32_t* __restrict__ Bqh, const uint32_t* __restrict__ Bql,
              const uint32_t* __restrict__ Bkh, const uint32_t* __restrict__ Bkl,
              const uint32_t* __restrict__ Bvh, const uint32_t* __restrict__ Bvl,
              const float* __restrict__ k1q, const float* __restrict__ k1k,
              const float* __restrict__ k1v,
              uint32_t* __restrict__ Qh, uint32_t* __restrict__ Ql,
              uint32_t* __restrict__ Kh, uint32_t* __restrict__ Kl,
              uint32_t* __restrict__ Vh, uint32_t* __restrict__ Vl)
{
    __shared__ GSmem sm;
    const int lin = blockIdx.z >> 1, half = blockIdx.z & 1;
    const uint32_t *Bh, *Bl; const float* k1; uint32_t *Yh, *Yl; float sc_;
    if (lin == 0)      { Bh = Bqh; Bl = Bql; k1 = k1q; Yh = Qh; Yl = Ql; sc_ = 0.125f; }
    else if (lin == 1) { Bh = Bkh; Bl = Bkl; k1 = k1k; Yh = Kh; Yl = Kl; sc_ = 1.0f; }
    else               { Bh = Bvh; Bl = Bvl; k1 = k1v; Yh = Vh; Yl = Vl; sc_ = 1.0f; }
    const uint32_t* Ah = Azh + (half ? XR : XI);
    const uint32_t* Al = Azl + (half ? XR : XI);
    const uint32_t* Bhs = Bh + (half ? 2 * BSEG : BSEG);
    const uint32_t* Bls = Bl + (half ? 2 * BSEG : BSEG);
    gemm_body(sm, Ah, Al, Bhs, Bls, k1, Yh, Yl, half ? 512 : 0, nullptr, 1, sc_);
}

__global__ void __launch_bounds__(128, 3)
gemm_k1_o(const uint32_t* __restrict__ Ah, const uint32_t* __restrict__ Al,
          const uint32_t* __restrict__ Bh, const uint32_t* __restrict__ Bl,
          float* __restrict__ k1o)
{
    __shared__ GSmem sm;
    gemm_body(sm, Ah, Al, Bh, Bl, nullptr, nullptr, nullptr, 0, k1o, 0, 1.0f);
}

__global__ void __launch_bounds__(128, 3)
gemm_comb_o(const uint32_t* __restrict__ Aoh, const uint32_t* __restrict__ Aol,
            const uint32_t* __restrict__ Bh, const uint32_t* __restrict__ Bl,
            const float* __restrict__ k1o,
            float* __restrict__ Yr, float* __restrict__ Yi)
{
    __shared__ GSmem sm;
    const int half = blockIdx.z;
    const uint32_t* Ah = Aoh + (half ? XR : XI);
    const uint32_t* Al = Aol + (half ? XR : XI);
    const uint32_t* Bhs = Bh + (half ? 2 * BSEG : BSEG);
    const uint32_t* Bls = Bl + (half ? 2 * BSEG : BSEG);
    gemm_body(sm, Ah, Al, Bhs, Bls, k1o, nullptr, nullptr, 0,
              half ? Yi : Yr, 2, 1.0f);
}

// ---------------------------------------------------------------------------
// Flash attention bf16x3 (R12 verbatim: ldmatrix.x4 Q, ldmatrix.x2 K).
// ---------------------------------------------------------------------------
struct FSmem {
    uint32_t Qh[128][68], Ql[128][68];
    uint32_t Kh[2][64][68], Kl[2][64][68];
    uint32_t Vh[32][136], Vl[32][136];
};

__global__ void __launch_bounds__(256, 1)
flash_bf16x3(const uint32_t* __restrict__ Qph, const uint32_t* __restrict__ Qpl,
             const uint32_t* __restrict__ Kph, const uint32_t* __restrict__ Kpl,
             const uint32_t* __restrict__ Vph, const uint32_t* __restrict__ Vpl,
             uint32_t* __restrict__ Aoh, uint32_t* __restrict__ Aol)
{
    extern __shared__ char raw[];
    FSmem& s = *reinterpret_cast<FSmem*>(raw);

    const int tid = threadIdx.x;
    const int w = tid >> 5, lane = tid & 31;
    const int grp = lane >> 2, tk = lane & 3;
    const int m0 = w * 16;
    const int lrow = lane & 15;
    const int lcol = (lane >> 4) * 4;
    const int krow = lane & 7;
    const int kcol = ((lane >> 3) & 1) * 4;
    const int bh = blockIdx.y;
    const int b = bh >> 4, h = bh & 15;
    const int qt = blockIdx.x;
    const size_t tokb = (size_t)b * SEQ;
    const int cph = h * 32;

    auto fillK = [&](int buf, int kt) {
        #pragma unroll
        for (int it = 0; it < 8; it++) {
            int task = tid + it * 256;
            int t2 = task & 1023;
            int r = t2 >> 4, cj = t2 & 15;
            int jj = (cj < 8) ? (cph + cj * 4) : (512 + cph + (cj - 8) * 4);
            const uint32_t* src = (task < 1024 ? Kph : Kpl) + (tokb + kt * 64 + r) * KP + jj;
            if (task < 1024) cpa16(&s.Kh[buf][r][cj * 4], src);
            else             cpa16(&s.Kl[buf][r][cj * 4], src);
        }
        CP_COMMIT();
    };

    auto fillV = [&](int kt) {
        #pragma unroll
        for (int it = 0; it < 4; it++) {
            int task = tid + it * 256;
            int t2 = task & 511;
            int p = t2 >> 4, cj = t2 & 15;
            int jj = (cj < 8) ? (cph + cj * 4) : (512 + cph + (cj - 8) * 4);
            int db = (cj < 8) ? (cj * 8) : (64 + (cj - 8) * 8);
            const uint32_t* base = (task < 512) ? Vph : Vpl;
            const uint32_t* r0 = base + (tokb + kt * 64 + 2 * p) * KP + jj;
            uint4 a4 = *(const uint4*)r0;
            uint4 b4 = *(const uint4*)(r0 + KP);
            uint32_t* dst = (task < 512) ? &s.Vh[p][db] : &s.Vl[p][db];
            dst[0] = __byte_perm(a4.x, b4.x, 0x5410);
            dst[1] = __byte_perm(a4.x, b4.x, 0x7632);
            dst[2] = __byte_perm(a4.y, b4.y, 0x5410);
            dst[3] = __byte_perm(a4.y, b4.y, 0x7632);
            dst[4] = __byte_perm(a4.z, b4.z, 0x5410);
            dst[5] = __byte_perm(a4.z, b4.z, 0x7632);
            dst[6] = __byte_perm(a4.w, b4.w, 0x5410);
            dst[7] = __byte_perm(a4.w, b4.w, 0x7632);
        }
    };

    fillK(0, 0);
    #pragma unroll
    for (int it = 0; it < 16; it++) {
        int task = tid + it * 256;
        int t2 = task & 2047;
        int r = t2 >> 4, cj = t2 & 15;
        int jj = (cj < 8) ? (cph + cj * 4) : (512 + cph + (cj - 8) * 4);
        const uint32_t* src = (task < 2048 ? Qph : Qpl) + (tokb + qt * 128 + r) * KP + jj;
        uint4 v = *(const uint4*)src;
        uint32_t* dst = (task < 2048) ? &s.Qh[r][cj * 4] : &s.Ql[r][cj * 4];
        dst[0] = v.x; dst[1] = v.y; dst[2] = v.z; dst[3] = v.w;
    }
    fillV(0);
    asm volatile("cp.async.wait_group 0;\n" ::: "memory");
    __syncthreads();

    float m0f = -1e30f, m1f = -1e30f, l0f = 0.0f, l1f = 0.0f;
    float o[16][4];
    #pragma unroll
    for (int di = 0; di < 16; di++)
        #pragma unroll
        for (int v = 0; v < 4; v++) o[di][v] = 0.0f;

    for (int kt = 0; kt < SEQ / 64; kt++) {
        const int cur = kt & 1;
        if (kt + 1 < SEQ / 64) fillK(cur ^ 1, kt + 1);

        float sc[8][4];
        #pragma unroll
        for (int ni = 0; ni < 8; ni++)
            #pragma unroll
            for (int v = 0; v < 4; v++) sc[ni][v] = 0.0f;

        #pragma unroll
        for (int kk = 0; kk < 8; kk++) {
            uint32_t afh[4], afl[4];
            ldsm4(afh, &s.Qh[m0 + lrow][kk * 8 + lcol]);
            ldsm4(afl, &s.Ql[m0 + lrow][kk * 8 + lcol]);
            #pragma unroll
            for (int ni = 0; ni < 8; ni++) {
                uint32_t bfh[2], bfl[2];
                ldsm2(bfh, &s.Kh[cur][ni * 8 + krow][kk * 8 + kcol]);
                ldsm2(bfl, &s.Kl[cur][ni * 8 + krow][kk * 8 + kcol]);
                mma16(sc[ni], afh, bfh);
                mma16(sc[ni], afh, bfl);
                mma16(sc[ni], afl, bfh);
            }
        }

        float mx0 = -1e30f, mx1 = -1e30f;
        #pragma unroll
        for (int ni = 0; ni < 8; ni++) {
            mx0 = fmaxf(mx0, fmaxf(sc[ni][0], sc[ni][1]));
            mx1 = fmaxf(mx1, fmaxf(sc[ni][2], sc[ni][3]));
        }
        mx0 = fmaxf(mx0, __shfl_xor_sync(0xffffffffu, mx0, 1));
        mx0 = fmaxf(mx0, __shfl_xor_sync(0xffffffffu, mx0, 2));
        mx1 = fmaxf(mx1, __shfl_xor_sync(0xffffffffu, mx1, 1));
        mx1 = fmaxf(mx1, __shfl_xor_sync(0xffffffffu, mx1, 2));
        float mn0 = fmaxf(m0f, mx0), mn1 = fmaxf(m1f, mx1);
        float al0 = __expf(m0f - mn0), al1 = __expf(m1f - mn1);
        m0f = mn0; m1f = mn1;
        float ls0 = 0.0f, ls1 = 0.0f;
        #pragma unroll
        for (int ni = 0; ni < 8; ni++) {
            sc[ni][0] = __expf(sc[ni][0] - mn0);
            sc[ni][1] = __expf(sc[ni][1] - mn0);
            sc[ni][2] = __expf(sc[ni][2] - mn1);
            sc[ni][3] = __expf(sc[ni][3] - mn1);
            ls0 += sc[ni][0] + sc[ni][1];
            ls1 += sc[ni][2] + sc[ni][3];
        }
        ls0 += __shfl_xor_sync(0xffffffffu, ls0, 1);
        ls0 += __shfl_xor_sync(0xffffffffu, ls0, 2);
        ls1 += __shfl_xor_sync(0xffffffffu, ls1, 1);
        ls1 += __shfl_xor_sync(0xffffffffu, ls1, 2);
        l0f = l0f * al0 + ls0;
        l1f = l1f * al1 + ls1;

        uint32_t pah[4][4], pal[4][4];
        #pragma unroll
        for (int sp = 0; sp < 4; sp++) {
            cvt2(sc[2 * sp    ][0], sc[2 * sp    ][1], pah[sp][0], pal[sp][0]);
            cvt2(sc[2 * sp    ][2], sc[2 * sp    ][3], pah[sp][1], pal[sp][1]);
            cvt2(sc[2 * sp + 1][0], sc[2 * sp + 1][1], pah[sp][2], pal[sp][2]);
            cvt2(sc[2 * sp + 1][2], sc[2 * sp + 1][3], pah[sp][3], pal[sp][3]);
        }

        #pragma unroll
        for (int di = 0; di < 16; di++) {
            o[di][0] *= al0; o[di][1] *= al0;
            o[di][2] *= al1; o[di][3] *= al1;
        }
        #pragma unroll
        for (int sp = 0; sp < 4; sp++) {
            #pragma unroll
            for (int di = 0; di < 16; di++) {
                uint32_t bfh[2], bfl[2];
                bfh[0] = s.Vh[sp * 8 + tk    ][di * 8 + grp];
                bfh[1] = s.Vh[sp * 8 + tk + 4][di * 8 + grp];
                bfl[0] = s.Vl[sp * 8 + tk    ][di * 8 + grp];
                bfl[1] = s.Vl[sp * 8 + tk + 4][di * 8 + grp];
                mma16(o[di], pah[sp], bfh);
                mma16(o[di], pah[sp], bfl);
                mma16(o[di], pal[sp], bfh);
            }
        }

        __syncthreads();
        if (kt + 1 < SEQ / 64) {
            fillV(kt + 1);
            asm volatile("cp.async.wait_group 0;\n" ::: "memory");
            __syncthreads();
        }
    }

    float li0 = 1.0f / l0f, li1 = 1.0f / l1f;
    int tok = b * SEQ + qt * 128;
    const size_t r0 = (size_t)(tok + m0 + grp) * AS;
    const size_t r1 = (size_t)(tok + m0 + grp + 8) * AS;
    #pragma unroll
    for (int di = 0; di < 8; di++) {
        int j = (h * HD >> 1) + di * 4 + tk;
        uint32_t hh, ll;
        cvt2(o[di][0] * li0, o[di][1] * li0, hh, ll);
        Aoh[r0 + XR + j] = hh; Aol[r0 + XR + j] = ll;
        cvt2(o[di][2] * li1, o[di][3] * li1, hh, ll);
        Aoh[r1 + XR + j] = hh; Aol[r1 + XR + j] = ll;
        cvt2(o[di + 8][0] * li0, o[di + 8][1] * li0, hh, ll);
        Aoh[r0 + XI + j] = hh; Aol[r0 + XI + j] = ll;
        cvt2(o[di + 8][2] * li1, o[di + 8][3] * li1, hh, ll);
        Aoh[r1 + XI + j] = hh; Aol[r1 + XI + j] = ll;
        cvt2((o[di][0] + o[di + 8][0]) * li0, (o[di][1] + o[di + 8][1]) * li0, hh, ll);
        Aoh[r0 + XA + j] = hh; Aol[r0 + XA + j] = ll;
        cvt2((o[di][2] + o[di + 8][2]) * li1, (o[di][3] + o[di + 8][3]) * li1, hh, ll);
        Aoh[r1 + XA + j] = hh; Aol[r1 + XA + j] = ll;
    }
}

// ---------------------------------------------------------------------------
extern "C" void kernel_launch(void* const* d_in, const int* in_sizes, int n_in,
                              void* d_out, int out_size)
{
    const float* zr   = (const float*)d_in[0];
    const float* zi   = (const float*)d_in[1];
    const float* wq_r = (const float*)d_in[2];
    const float* wq_i = (const float*)d_in[3];
    const float* wk_r = (const float*)d_in[4];
    const float* wk_i = (const float*)d_in[5];
    const float* wv_r = (const float*)d_in[6];
    const float* wv_i = (const float*)d_in[7];
    const float* wo_r = (const float*)d_in[8];
    const float* wo_i = (const float*)d_in[9];

    uint32_t* sc = nullptr;
    cudaGetSymbolAddress((void**)&sc, g_scratch);
    uint32_t* Azh = sc;
    uint32_t* Azl = sc + 6u * MEGA;
    const uint32_t BL = 3u * BSEG;
    uint32_t* Bq = sc + 12u * MEGA;
    uint32_t* Bqh = Bq;              uint32_t* Bql = Bq + BL;
    uint32_t* Bkh = Bq + 3u * MEGA;  uint32_t* Bkl = Bkh + BL;
    uint32_t* Bvh = Bq + 6u * MEGA;  uint32_t* Bvl = Bvh + BL;
    uint32_t* Boh = Bq + 9u * MEGA;  uint32_t* Bol = Boh + BL;
    uint32_t* Qh  = sc + 24u * MEGA;  uint32_t* Ql  = sc + 28u * MEGA;
    uint32_t* Kh  = sc + 32u * MEGA;  uint32_t* Kl  = sc + 36u * MEGA;
    uint32_t* Vh  = sc + 40u * MEGA;  uint32_t* Vl  = sc + 44u * MEGA;
    uint32_t* Aoh = sc + 48u * MEGA;  uint32_t* Aol = sc + 54u * MEGA;
    float* k1q = (float*)(sc + 60u * MEGA);
    float* k1k = (float*)(sc + 64u * MEGA);
    float* k1v = (float*)(sc + 68u * MEGA);
    float* k1o = k1q;

    float* yr = (float*)d_out;
    float* yi = (float*)d_out + NTD;

    pack_x<<<(NTOK * AS) / 256, 256>>>(zr, zi, Azh, Azl);
    dim3 pwg((512 * 1024) / 256, 4);
    pack_w3_all<<<pwg, 256>>>(wq_r, wq_i, wk_r, wk_i, wv_r, wv_i, wo_r, wo_i,
                              Bqh, Bql, Bkh, Bkl, Bvh, Bvl, Boh, Bol);

    dim3 g1(8, 32, 3);
    gemm_k1_qkv<<<g1, 128>>>(Azh + XA, Azl + XA, Bqh, Bql, Bkh, Bkl, Bvh, Bvl,
                             k1q, k1k, k1v);
    dim3 g2(8, 32, 6);
    gemm_comb_qkv<<<g2, 128>>>(Azh, Azl, Bqh, Bql, Bkh, Bkl, Bvh, Bvl,
                               k1q, k1k, k1v, Qh, Ql, Kh, Kl, Vh, Vl);

    static const int kSmem = (int)sizeof(FSmem);
    cudaFuncSetAttribute(flash_bf16x3, cudaFuncAttributeMaxDynamicSharedMemorySize, kSmem);
    dim3 fgrid(SEQ / 128, BATCH * NH);
    flash_bf16x3<<<fgrid, 256, kSmem>>>(Qh, Ql, Kh, Kl, Vh, Vl, Aoh, Aol);

    dim3 g3(8, 32);
    gemm_k1_o<<<g3, 128>>>(Aoh + XA, Aol + XA, Boh, Bol, k1o);
    dim3 g4(8, 32, 2);
    gemm_comb_o<<<g4, 128>>>(Aoh, Aol, Boh, Bol, k1o, yr, yi);
}

// round 16
// speedup vs baseline: 1.1292x; 1.1292x over previous
#include <cuda_runtime.h>
#include <cuda_bf16.h>
#include <math.h>
#include <stdint.h>

// ---------------------------------------------------------------------------
// HermitianAttention (B=2,S=2048,D=1024,H=16,hd=64) — bf16x3, pre-packed.
// R16 = R12 exactly (Karatsuba 3-mult linears, [kpair][n] weights,
// ldmatrix.x4 A/Q + ldmatrix.x2 K, launch_bounds(128,2)) + fused weight pack.
// ---------------------------------------------------------------------------

#define BATCH 2
#define SEQ   2048
#define DIMM  1024
#define NH    16
#define HD    64
#define NTOK  (BATCH * SEQ)
#define NTD   (NTOK * DIMM)
#define KP    1024
#define AS    1536
#define XR    0
#define XI    512
#define XA    1024

#define MEGA (1024u * 1024u)
__device__ uint32_t g_scratch[72u * MEGA];

__device__ __forceinline__ void cvt2(float x0, float x1, uint32_t& h, uint32_t& l) {
    __nv_bfloat16 h0 = __float2bfloat16_rn(x0);
    __nv_bfloat16 h1 = __float2bfloat16_rn(x1);
    float r0 = x0 - __bfloat162float(h0);
    float r1 = x1 - __bfloat162float(h1);
    __nv_bfloat16 l0 = __float2bfloat16_rn(r0);
    __nv_bfloat16 l1 = __float2bfloat16_rn(r1);
    h = ((uint32_t)__bfloat16_as_ushort(h1) << 16) | __bfloat16_as_ushort(h0);
    l = ((uint32_t)__bfloat16_as_ushort(l1) << 16) | __bfloat16_as_ushort(l0);
}

__device__ __forceinline__ void mma16(float c[4], const uint32_t a[4], const uint32_t b[2]) {
    asm volatile(
        "mma.sync.aligned.m16n8k16.row.col.f32.bf16.bf16.f32 "
        "{%0,%1,%2,%3}, {%4,%5,%6,%7}, {%8,%9}, {%0,%1,%2,%3};\n"
        : "+f"(c[0]), "+f"(c[1]), "+f"(c[2]), "+f"(c[3])
        : "r"(a[0]), "r"(a[1]), "r"(a[2]), "r"(a[3]), "r"(b[0]), "r"(b[1]));
}

__device__ __forceinline__ void cpa16(const void* dst, const void* src) {
    uint32_t d = (uint32_t)__cvta_generic_to_shared(dst);
    asm volatile("cp.async.cg.shared.global [%0], [%1], 16;\n" :: "r"(d), "l"(src));
}
#define CP_COMMIT() asm volatile("cp.async.commit_group;\n" ::: "memory")

__device__ __forceinline__ void ldsm4(uint32_t r[4], const void* p) {
    uint32_t a = (uint32_t)__cvta_generic_to_shared(p);
    asm volatile("ldmatrix.sync.aligned.m8n8.x4.shared.b16 {%0,%1,%2,%3}, [%4];"
        : "=r"(r[0]), "=r"(r[1]), "=r"(r[2]), "=r"(r[3]) : "r"(a));
}
__device__ __forceinline__ void ldsm2(uint32_t r[2], const void* p) {
    uint32_t a = (uint32_t)__cvta_generic_to_shared(p);
    asm volatile("ldmatrix.sync.aligned.m8n8.x2.shared.b16 {%0,%1}, [%2];"
        : "=r"(r[0]), "=r"(r[1]) : "r"(a));
}

// ---------------------------------------------------------------------------
// Pack kernels.
// ---------------------------------------------------------------------------
__global__ void pack_x(const float* __restrict__ zr, const float* __restrict__ zi,
                       uint32_t* __restrict__ Ah, uint32_t* __restrict__ Al)
{
    int p = blockIdx.x * blockDim.x + threadIdx.x;
    int m = p / AS, j = p % AS;
    int c = (j & 511) * 2;
    float a, b;
    if (j < 512)       { float2 v = *(const float2*)(zr + (size_t)m * DIMM + c); a = v.x; b = v.y; }
    else if (j < 1024) { float2 v = *(const float2*)(zi + (size_t)m * DIMM + c); a = v.x; b = v.y; }
    else {
        float2 vr = *(const float2*)(zr + (size_t)m * DIMM + c);
        float2 vi = *(const float2*)(zi + (size_t)m * DIMM + c);
        a = vr.x + vi.x; b = vr.y + vi.y;
    }
    uint32_t h, l; cvt2(a, b, h, l);
    Ah[p] = h; Al[p] = l;
}

#define BSEG (512u * 1024u)
// Fused over blockIdx.y: all 4 weight matrices in one launch.
__global__ void pack_w3_all(const float* __restrict__ Wq_r, const float* __restrict__ Wq_i,
                            const float* __restrict__ Wk_r, const float* __restrict__ Wk_i,
                            const float* __restrict__ Wv_r, const float* __restrict__ Wv_i,
                            const float* __restrict__ Wo_r, const float* __restrict__ Wo_i,
                            uint32_t* __restrict__ Bqh, uint32_t* __restrict__ Bql,
                            uint32_t* __restrict__ Bkh, uint32_t* __restrict__ Bkl,
                            uint32_t* __restrict__ Bvh, uint32_t* __restrict__ Bvl,
                            uint32_t* __restrict__ Boh, uint32_t* __restrict__ Bol)
{
    const float *Wr, *Wi; uint32_t *Bh, *Bl;
    if (blockIdx.y == 0)      { Wr = Wq_r; Wi = Wq_i; Bh = Bqh; Bl = Bql; }
    else if (blockIdx.y == 1) { Wr = Wk_r; Wi = Wk_i; Bh = Bkh; Bl = Bkl; }
    else if (blockIdx.y == 2) { Wr = Wv_r; Wi = Wv_i; Bh = Bvh; Bl = Bvl; }
    else                      { Wr = Wo_r; Wi = Wo_i; Bh = Boh; Bl = Bol; }

    int idx = blockIdx.x * blockDim.x + threadIdx.x;
    int n = idx & 1023, pp = idx >> 10;
    int k0 = 2 * pp;
    float wr0 = Wr[(size_t)k0 * DIMM + n], wr1 = Wr[(size_t)(k0 + 1) * DIMM + n];
    float wi0 = Wi[(size_t)k0 * DIMM + n], wi1 = Wi[(size_t)(k0 + 1) * DIMM + n];
    uint32_t h, l;
    size_t o = (size_t)pp * 1024 + n;
    cvt2(wr0, wr1, h, l);                    Bh[o] = h;            Bl[o] = l;
    cvt2(-(wr0 + wi0), -(wr1 + wi1), h, l);  Bh[o + BSEG] = h;     Bl[o + BSEG] = l;
    cvt2(wi0 - wr0, wi1 - wr1, h, l);        Bh[o + 2 * BSEG] = h; Bl[o + 2 * BSEG] = l;
}

// ---------------------------------------------------------------------------
// bf16x3 GEMM (R12 verbatim). M=4096, Kpairs=512, N=1024. BM=BN=128,
// BK=16 pairs, 32 stages, 2-stage cp.async. 128 threads, warp tile 64x64.
// ---------------------------------------------------------------------------
struct GSmem {
    uint32_t Ah[2][128][20], Al[2][128][20];
    uint32_t Bh[2][16][136], Bl[2][16][136];
};

__device__ __forceinline__ void
gemm_body(GSmem& sm,
          const uint32_t* __restrict__ Ah, const uint32_t* __restrict__ Al,
          const uint32_t* __restrict__ Bh, const uint32_t* __restrict__ Bl,
          const float* __restrict__ k1,
          uint32_t* __restrict__ Yh, uint32_t* __restrict__ Yl, int co,
          float* __restrict__ Yf, int mode, float oscale)
{
    const int tid = threadIdx.x;
    const int w = tid >> 5, lane = tid & 31;
    const int grp = lane >> 2, tk = lane & 3;
    const int warpM = (w >> 1) * 64;
    const int warpN = (w & 1) * 64;
    const int bm = blockIdx.y * 128;
    const int bn = blockIdx.x * 128;
    const int lrow = lane & 15;
    const int lcol = (lane >> 4) * 4;

    float acc[4][8][4];
    #pragma unroll
    for (int mi = 0; mi < 4; mi++)
        #pragma unroll
        for (int ni = 0; ni < 8; ni++)
            #pragma unroll
            for (int v = 0; v < 4; v++) acc[mi][ni][v] = 0.0f;

    auto fill = [&](int s, int kp) {
        #pragma unroll
        for (int it = 0; it < 8; it++) {
            int t = tid + it * 128;
            int t2 = t & 511;
            int r = t2 >> 2, c = (t2 & 3) * 4;
            const uint32_t* src = (t < 512 ? Ah : Al) + (size_t)(bm + r) * AS + kp + c;
            if (t < 512) cpa16(&sm.Ah[s][r][c], src);
            else         cpa16(&sm.Al[s][r][c], src);
        }
        #pragma unroll
        for (int it = 0; it < 8; it++) {
            int t = tid + it * 128;
            int t2 = t & 511;
            int p = t2 >> 5, c = (t2 & 31) * 4;
            const uint32_t* src = (t < 512 ? Bh : Bl) + (size_t)(kp + p) * 1024 + bn + c;
            if (t < 512) cpa16(&sm.Bh[s][p][c], src);
            else         cpa16(&sm.Bl[s][p][c], src);
        }
    };

    fill(0, 0);
    CP_COMMIT();

    for (int st = 0; st < 32; st++) {
        int cur = st & 1;
        if (st + 1 < 32) {
            fill(cur ^ 1, (st + 1) * 16);
            CP_COMMIT();
            asm volatile("cp.async.wait_group 1;\n" ::: "memory");
        } else {
            asm volatile("cp.async.wait_group 0;\n" ::: "memory");
        }
        __syncthreads();

        #pragma unroll
        for (int kk = 0; kk < 2; kk++) {
            uint32_t afh[4][4], afl[4][4];
            #pragma unroll
            for (int mi = 0; mi < 4; mi++) {
                int m0 = warpM + mi * 16;
                ldsm4(afh[mi], &sm.Ah[cur][m0 + lrow][kk * 8 + lcol]);
                ldsm4(afl[mi], &sm.Al[cur][m0 + lrow][kk * 8 + lcol]);
            }
            #pragma unroll
            for (int ni = 0; ni < 8; ni++) {
                int n0 = warpN + ni * 8;
                uint32_t bfh[2], bfl[2];
                bfh[0] = sm.Bh[cur][kk * 8 + tk    ][n0 + grp];
                bfh[1] = sm.Bh[cur][kk * 8 + tk + 4][n0 + grp];
                bfl[0] = sm.Bl[cur][kk * 8 + tk    ][n0 + grp];
                bfl[1] = sm.Bl[cur][kk * 8 + tk + 4][n0 + grp];
                #pragma unroll
                for (int mi = 0; mi < 4; mi++) {
                    mma16(acc[mi][ni], afh[mi], bfh);
                    mma16(acc[mi][ni], afh[mi], bfl);
                    mma16(acc[mi][ni], afl[mi], bfh);
                }
            }
        }
        __syncthreads();
    }

    #pragma unroll
    for (int mi = 0; mi < 4; mi++) {
        int m = bm + warpM + mi * 16 + grp;
        #pragma unroll
        for (int ni = 0; ni < 8; ni++) {
            int n = bn + warpN + ni * 8 + tk * 2;
            if (mode == 0) {
                *(float2*)(Yf + (size_t)m * 1024 + n) =
                    make_float2(acc[mi][ni][0], acc[mi][ni][1]);
                *(float2*)(Yf + (size_t)(m + 8) * 1024 + n) =
                    make_float2(acc[mi][ni][2], acc[mi][ni][3]);
            } else {
                float2 k0 = *(const float2*)(k1 + (size_t)m * 1024 + n);
                float2 k8 = *(const float2*)(k1 + (size_t)(m + 8) * 1024 + n);
                float v0 = acc[mi][ni][0] + k0.x, v1 = acc[mi][ni][1] + k0.y;
                float v2 = acc[mi][ni][2] + k8.x, v3 = acc[mi][ni][3] + k8.y;
                if (mode == 1) {
                    uint32_t h, l;
                    int col = co + (n >> 1);
                    cvt2(v0 * oscale, v1 * oscale, h, l);
                    Yh[(size_t)m * KP + col] = h;
                    Yl[(size_t)m * KP + col] = l;
                    cvt2(v2 * oscale, v3 * oscale, h, l);
                    Yh[(size_t)(m + 8) * KP + col] = h;
                    Yl[(size_t)(m + 8) * KP + col] = l;
                } else {
                    *(float2*)(Yf + (size_t)m * 1024 + n) = make_float2(v0, v1);
                    *(float2*)(Yf + (size_t)(m + 8) * 1024 + n) = make_float2(v2, v3);
                }
            }
        }
    }
}

__global__ void __launch_bounds__(128, 2)
gemm_k1_qkv(const uint32_t* __restrict__ Ah, const uint32_t* __restrict__ Al,
            const uint32_t* __restrict__ Bqh, const uint32_t* __restrict__ Bql,
            const uint32_t* __restrict__ Bkh, const uint32_t* __restrict__ Bkl,
            const uint32_t* __restrict__ Bvh, const uint32_t* __restrict__ Bvl,
            float* __restrict__ k1q, float* __restrict__ k1k, float* __restrict__ k1v)
{
    __shared__ GSmem sm;
    const uint32_t *Bh, *Bl; float* Yf;
    if (blockIdx.z == 0)      { Bh = Bqh; Bl = Bql; Yf = k1q; }
    else if (blockIdx.z == 1) { Bh = Bkh; Bl = Bkl; Yf = k1k; }
    else                      { Bh = Bvh; Bl = Bvl; Yf = k1v; }
    gemm_body(sm, Ah, Al, Bh, Bl, nullptr, nullptr, nullptr, 0, Yf, 0, 1.0f);
}

__global__ void __launch_bounds__(128, 2)
gemm_comb_qkv(const uint32_t* __restrict__ Azh, const uint32_t* __restrict__ Azl,
              const uint32_t* __restrict__ Bqh, const uint32_t* __restrict__ Bql,
              const uint32_t* __restrict__ Bkh, const uint32_t* __restrict__ Bkl,
              const uint32_t* __restrict__ Bvh, const uint32_t* __restrict__ Bvl,
              const float* __restrict__ k1q, const float* __restrict__ k1k,
              const float* __restrict__ k1v,
              uint32_t* __restrict__ Qh, uint32_t* __restrict__ Ql,
              uint32_t* __restrict__ Kh, uint32_t* __restrict__ Kl,
              uint32_t* __restrict__ Vh, uint32_t* __restrict__ Vl)
{
    __shared__ GSmem sm;
    const int lin = blockIdx.z >> 1, half = blockIdx.z & 1;
    const uint32_t *Bh, *Bl; const float* k1; uint32_t *Yh, *Yl; float sc_;
    if (lin == 0)      { Bh = Bqh; Bl = Bql; k1 = k1q; Yh = Qh; Yl = Ql; sc_ = 0.125f; }
    else if (lin == 1) { Bh = Bkh; Bl = Bkl; k1 = k1k; Yh = Kh; Yl = Kl; sc_ = 1.0f; }
    else               { Bh = Bvh; Bl = Bvl; k1 = k1v; Yh = Vh; Yl = Vl; sc_ = 1.0f; }
    const uint32_t* Ah = Azh + (half ? XR : XI);
    const uint32_t* Al = Azl + (half ? XR : XI);
    const uint32_t* Bhs = Bh + (half ? 2 * BSEG : BSEG);
    const uint32_t* Bls = Bl + (half ? 2 * BSEG : BSEG);
    gemm_body(sm, Ah, Al, Bhs, Bls, k1, Yh, Yl, half ? 512 : 0, nullptr, 1, sc_);
}

__global__ void __launch_bounds__(128, 2)
gemm_k1_o(const uint32_t* __restrict__ Ah, const uint32_t* __restrict__ Al,
          const uint32_t* __restrict__ Bh, const uint32_t* __restrict__ Bl,
          float* __restrict__ k1o)
{
    __shared__ GSmem sm;
    gemm_body(sm, Ah, Al, Bh, Bl, nullptr, nullptr, nullptr, 0, k1o, 0, 1.0f);
}

__global__ void __launch_bounds__(128, 2)
gemm_comb_o(const uint32_t* __restrict__ Aoh, const uint32_t* __restrict__ Aol,
            const uint32_t* __restrict__ Bh, const uint32_t* __restrict__ Bl,
            const float* __restrict__ k1o,
            float* __restrict__ Yr, float* __restrict__ Yi)
{
    __shared__ GSmem sm;
    const int half = blockIdx.z;
    const uint32_t* Ah = Aoh + (half ? XR : XI);
    const uint32_t* Al = Aol + (half ? XR : XI);
    const uint32_t* Bhs = Bh + (half ? 2 * BSEG : BSEG);
    const uint32_t* Bls = Bl + (half ? 2 * BSEG : BSEG);
    gemm_body(sm, Ah, Al, Bhs, Bls, k1o, nullptr, nullptr, 0,
              half ? Yi : Yr, 2, 1.0f);
}

// ---------------------------------------------------------------------------
// Flash attention bf16x3 (R12 verbatim: ldmatrix.x4 Q, ldmatrix.x2 K).
// ---------------------------------------------------------------------------
struct FSmem {
    uint32_t Qh[128][68], Ql[128][68];
    uint32_t Kh[2][64][68], Kl[2][64][68];
    uint32_t Vh[32][136], Vl[32][136];
};

__global__ void __launch_bounds__(256, 1)
flash_bf16x3(const uint32_t* __restrict__ Qph, const uint32_t* __restrict__ Qpl,
             const uint32_t* __restrict__ Kph, const uint32_t* __restrict__ Kpl,
             const uint32_t* __restrict__ Vph, const uint32_t* __restrict__ Vpl,
             uint32_t* __restrict__ Aoh, uint32_t* __restrict__ Aol)
{
    extern __shared__ char raw[];
    FSmem& s = *reinterpret_cast<FSmem*>(raw);

    const int tid = threadIdx.x;
    const int w = tid >> 5, lane = tid & 31;
    const int grp = lane >> 2, tk = lane & 3;
    const int m0 = w * 16;
    const int lrow = lane & 15;
    const int lcol = (lane >> 4) * 4;
    const int krow = lane & 7;
    const int kcol = ((lane >> 3) & 1) * 4;
    const int bh = blockIdx.y;
    const int b = bh >> 4, h = bh & 15;
    const int qt = blockIdx.x;
    const size_t tokb = (size_t)b * SEQ;
    const int cph = h * 32;

    auto fillK = [&](int buf, int kt) {
        #pragma unroll
        for (int it = 0; it < 8; it++) {
            int task = tid + it * 256;
            int t2 = task & 1023;
            int r = t2 >> 4, cj = t2 & 15;
            int jj = (cj < 8) ? (cph + cj * 4) : (512 + cph + (cj - 8) * 4);
            const uint32_t* src = (task < 1024 ? Kph : Kpl) + (tokb + kt * 64 + r) * KP + jj;
            if (task < 1024) cpa16(&s.Kh[buf][r][cj * 4], src);
            else             cpa16(&s.Kl[buf][r][cj * 4], src);
        }
        CP_COMMIT();
    };

    auto fillV = [&](int kt) {
        #pragma unroll
        for (int it = 0; it < 4; it++) {
            int task = tid + it * 256;
            int t2 = task & 511;
            int p = t2 >> 4, cj = t2 & 15;
            int jj = (cj < 8) ? (cph + cj * 4) : (512 + cph + (cj - 8) * 4);
            int db = (cj < 8) ? (cj * 8) : (64 + (cj - 8) * 8);
            const uint32_t* base = (task < 512) ? Vph : Vpl;
            const uint32_t* r0 = base + (tokb + kt * 64 + 2 * p) * KP + jj;
            uint4 a4 = *(const uint4*)r0;
            uint4 b4 = *(const uint4*)(r0 + KP);
            uint32_t* dst = (task < 512) ? &s.Vh[p][db] : &s.Vl[p][db];
            dst[0] = __byte_perm(a4.x, b4.x, 0x5410);
            dst[1] = __byte_perm(a4.x, b4.x, 0x7632);
            dst[2] = __byte_perm(a4.y, b4.y, 0x5410);
            dst[3] = __byte_perm(a4.y, b4.y, 0x7632);
            dst[4] = __byte_perm(a4.z, b4.z, 0x5410);
            dst[5] = __byte_perm(a4.z, b4.z, 0x7632);
            dst[6] = __byte_perm(a4.w, b4.w, 0x5410);
            dst[7] = __byte_perm(a4.w, b4.w, 0x7632);
        }
    };

    fillK(0, 0);
    #pragma unroll
    for (int it = 0; it < 16; it++) {
        int task = tid + it * 256;
        int t2 = task & 2047;
        int r = t2 >> 4, cj = t2 & 15;
        int jj = (cj < 8) ? (cph + cj * 4) : (512 + cph + (cj - 8) * 4);
        const uint32_t* src = (task < 2048 ? Qph : Qpl) + (tokb + qt * 128 + r) * KP + jj;
        uint4 v = *(const uint4*)src;
        uint32_t* dst = (task < 2048) ? &s.Qh[r][cj * 4] : &s.Ql[r][cj * 4];
        dst[0] = v.x; dst[1] = v.y; dst[2] = v.z; dst[3] = v.w;
    }
    fillV(0);
    asm volatile("cp.async.wait_group 0;\n" ::: "memory");
    __syncthreads();

    float m0f = -1e30f, m1f = -1e30f, l0f = 0.0f, l1f = 0.0f;
    float o[16][4];
    #pragma unroll
    for (int di = 0; di < 16; di++)
        #pragma unroll
        for (int v = 0; v < 4; v++) o[di][v] = 0.0f;

    for (int kt = 0; kt < SEQ / 64; kt++) {
        const int cur = kt & 1;
        if (kt + 1 < SEQ / 64) fillK(cur ^ 1, kt + 1);

        float sc[8][4];
        #pragma unroll
        for (int ni = 0; ni < 8; ni++)
            #pragma unroll
            for (int v = 0; v < 4; v++) sc[ni][v] = 0.0f;

        #pragma unroll
        for (int kk = 0; kk < 8; kk++) {
            uint32_t afh[4], afl[4];
            ldsm4(afh, &s.Qh[m0 + lrow][kk * 8 + lcol]);
            ldsm4(afl, &s.Ql[m0 + lrow][kk * 8 + lcol]);
            #pragma unroll
            for (int ni = 0; ni < 8; ni++) {
                uint32_t bfh[2], bfl[2];
                ldsm2(bfh, &s.Kh[cur][ni * 8 + krow][kk * 8 + kcol]);
                ldsm2(bfl, &s.Kl[cur][ni * 8 + krow][kk * 8 + kcol]);
                mma16(sc[ni], afh, bfh);
                mma16(sc[ni], afh, bfl);
                mma16(sc[ni], afl, bfh);
            }
        }

        float mx0 = -1e30f, mx1 = -1e30f;
        #pragma unroll
        for (int ni = 0; ni < 8; ni++) {
            mx0 = fmaxf(mx0, fmaxf(sc[ni][0], sc[ni][1]));
            mx1 = fmaxf(mx1, fmaxf(sc[ni][2], sc[ni][3]));
        }
        mx0 = fmaxf(mx0, __shfl_xor_sync(0xffffffffu, mx0, 1));
        mx0 = fmaxf(mx0, __shfl_xor_sync(0xffffffffu, mx0, 2));
        mx1 = fmaxf(mx1, __shfl_xor_sync(0xffffffffu, mx1, 1));
        mx1 = fmaxf(mx1, __shfl_xor_sync(0xffffffffu, mx1, 2));
        float mn0 = fmaxf(m0f, mx0), mn1 = fmaxf(m1f, mx1);
        float al0 = __expf(m0f - mn0), al1 = __expf(m1f - mn1);
        m0f = mn0; m1f = mn1;
        float ls0 = 0.0f, ls1 = 0.0f;
        #pragma unroll
        for (int ni = 0; ni < 8; ni++) {
            sc[ni][0] = __expf(sc[ni][0] - mn0);
            sc[ni][1] = __expf(sc[ni][1] - mn0);
            sc[ni][2] = __expf(sc[ni][2] - mn1);
            sc[ni][3] = __expf(sc[ni][3] - mn1);
            ls0 += sc[ni][0] + sc[ni][1];
            ls1 += sc[ni][2] + sc[ni][3];
        }
        ls0 += __shfl_xor_sync(0xffffffffu, ls0, 1);
        ls0 += __shfl_xor_sync(0xffffffffu, ls0, 2);
        ls1 += __shfl_xor_sync(0xffffffffu, ls1, 1);
        ls1 += __shfl_xor_sync(0xffffffffu, ls1, 2);
        l0f = l0f * al0 + ls0;
        l1f = l1f * al1 + ls1;

        uint32_t pah[4][4], pal[4][4];
        #pragma unroll
        for (int sp = 0; sp < 4; sp++) {
            cvt2(sc[2 * sp    ][0], sc[2 * sp    ][1], pah[sp][0], pal[sp][0]);
            cvt2(sc[2 * sp    ][2], sc[2 * sp    ][3], pah[sp][1], pal[sp][1]);
            cvt2(sc[2 * sp + 1][0], sc[2 * sp + 1][1], pah[sp][2], pal[sp][2]);
            cvt2(sc[2 * sp + 1][2], sc[2 * sp + 1][3], pah[sp][3], pal[sp][3]);
        }

        #pragma unroll
        for (int di = 0; di < 16; di++) {
            o[di][0] *= al0; o[di][1] *= al0;
            o[di][2] *= al1; o[di][3] *= al1;
        }
        #pragma unroll
        for (int sp = 0; sp < 4; sp++) {
            #pragma unroll
            for (int di = 0; di < 16; di++) {
                uint32_t bfh[2], bfl[2];
                bfh[0] = s.Vh[sp * 8 + tk    ][di * 8 + grp];
                bfh[1] = s.Vh[sp * 8 + tk + 4][di * 8 + grp];
                bfl[0] = s.Vl[sp * 8 + tk    ][di * 8 + grp];
                bfl[1] = s.Vl[sp * 8 + tk + 4][di * 8 + grp];
                mma16(o[di], pah[sp], bfh);
                mma16(o[di], pah[sp], bfl);
                mma16(o[di], pal[sp], bfh);
            }
        }

        __syncthreads();
        if (kt + 1 < SEQ / 64) {
            fillV(kt + 1);
            asm volatile("cp.async.wait_group 0;\n" ::: "memory");
            __syncthreads();
        }
    }

    float li0 = 1.0f / l0f, li1 = 1.0f / l1f;
    int tok = b * SEQ + qt * 128;
    const size_t r0 = (size_t)(tok + m0 + grp) * AS;
    const size_t r1 = (size_t)(tok + m0 + grp + 8) * AS;
    #pragma unroll
    for (int di = 0; di < 8; di++) {
        int j = (h * HD >> 1) + di * 4 + tk;
        uint32_t hh, ll;
        cvt2(o[di][0] * li0, o[di][1] * li0, hh, ll);
        Aoh[r0 + XR + j] = hh; Aol[r0 + XR + j] = ll;
        cvt2(o[di][2] * li1, o[di][3] * li1, hh, ll);
        Aoh[r1 + XR + j] = hh; Aol[r1 + XR + j] = ll;
        cvt2(o[di + 8][0] * li0, o[di + 8][1] * li0, hh, ll);
        Aoh[r0 + XI + j] = hh; Aol[r0 + XI + j] = ll;
        cvt2(o[di + 8][2] * li1, o[di + 8][3] * li1, hh, ll);
        Aoh[r1 + XI + j] = hh; Aol[r1 + XI + j] = ll;
        cvt2((o[di][0] + o[di + 8][0]) * li0, (o[di][1] + o[di + 8][1]) * li0, hh, ll);
        Aoh[r0 + XA + j] = hh; Aol[r0 + XA + j] = ll;
        cvt2((o[di][2] + o[di + 8][2]) * li1, (o[di][3] + o[di + 8][3]) * li1, hh, ll);
        Aoh[r1 + XA + j] = hh; Aol[r1 + XA + j] = ll;
    }
}

// ---------------------------------------------------------------------------
extern "C" void kernel_launch(void* const* d_in, const int* in_sizes, int n_in,
                              void* d_out, int out_size)
{
    const float* zr   = (const float*)d_in[0];
    const float* zi   = (const float*)d_in[1];
    const float* wq_r = (const float*)d_in[2];
    const float* wq_i = (const float*)d_in[3];
    const float* wk_r = (const float*)d_in[4];
    const float* wk_i = (const float*)d_in[5];
    const float* wv_r = (const float*)d_in[6];
    const float* wv_i = (const float*)d_in[7];
    const float* wo_r = (const float*)d_in[8];
    const float* wo_i = (const float*)d_in[9];

    uint32_t* sc = nullptr;
    cudaGetSymbolAddress((void**)&sc, g_scratch);
    uint32_t* Azh = sc;
    uint32_t* Azl = sc + 6u * MEGA;
    const uint32_t BL = 3u * BSEG;
    uint32_t* Bq = sc + 12u * MEGA;
    uint32_t* Bqh = Bq;              uint32_t* Bql = Bq + BL;
    uint32_t* Bkh = Bq + 3u * MEGA;  uint32_t* Bkl = Bkh + BL;
    uint32_t* Bvh = Bq + 6u * MEGA;  uint32_t* Bvl = Bvh + BL;
    uint32_t* Boh = Bq + 9u * MEGA;  uint32_t* Bol = Boh + BL;
    uint32_t* Qh  = sc + 24u * MEGA;  uint32_t* Ql  = sc + 28u * MEGA;
    uint32_t* Kh  = sc + 32u * MEGA;  uint32_t* Kl  = sc + 36u * MEGA;
    uint32_t* Vh  = sc + 40u * MEGA;  uint32_t* Vl  = sc + 44u * MEGA;
    uint32_t* Aoh = sc + 48u * MEGA;  uint32_t* Aol = sc + 54u * MEGA;
    float* k1q = (float*)(sc + 60u * MEGA);
    float* k1k = (float*)(sc + 64u * MEGA);
    float* k1v = (float*)(sc + 68u * MEGA);
    float* k1o = k1q;

    float* yr = (float*)d_out;
    float* yi = (float*)d_out + NTD;

    pack_x<<<(NTOK * AS) / 256, 256>>>(zr, zi, Azh, Azl);
    dim3 pwg((512 * 1024) / 256, 4);
    pack_w3_all<<<pwg, 256>>>(wq_r, wq_i, wk_r, wk_i, wv_r, wv_i, wo_r, wo_i,
                              Bqh, Bql, Bkh, Bkl, Bvh, Bvl, Boh, Bol);

    dim3 g1(8, 32, 3);
    gemm_k1_qkv<<<g1, 128>>>(Azh + XA, Azl + XA, Bqh, Bql, Bkh, Bkl, Bvh, Bvl,
                             k1q, k1k, k1v);
    dim3 g2(8, 32, 6);
    gemm_comb_qkv<<<g2, 128>>>(Azh, Azl, Bqh, Bql, Bkh, Bkl, Bvh, Bvl,
                               k1q, k1k, k1v, Qh, Ql, Kh, Kl, Vh, Vl);

    static const int kSmem = (int)sizeof(FSmem);
    cudaFuncSetAttribute(flash_bf16x3, cudaFuncAttributeMaxDynamicSharedMemorySize, kSmem);
    dim3 fgrid(SEQ / 128, BATCH * NH);
    flash_bf16x3<<<fgrid, 256, kSmem>>>(Qh, Ql, Kh, Kl, Vh, Vl, Aoh, Aol);

    dim3 g3(8, 32);
    gemm_k1_o<<<g3, 128>>>(Aoh + XA, Aol + XA, Boh, Bol, k1o);
    dim3 g4(8, 32, 2);
    gemm_comb_o<<<g4, 128>>>(Aoh, Aol, Boh, Bol, k1o, yr, yi);
}